// round 5
// baseline (speedup 1.0000x reference)
#include <cuda_runtime.h>
#include <cooperative_groups.h>

namespace cg = cooperative_groups;

#define N_QUBITS 15
#define N_LAYERS 4
#define BATCHN   64
#define NSTATE   (1 << N_QUBITS)   // 32768
#define NTHREADS 512

// 16 MB L2-resident state scratch: [batch][32768] complex64 as float2.
__device__ float2 g_state[BATCHN * NSTATE];

__device__ __forceinline__ void crot(float2& a0, float2& a1,
                                     float2 u0, float2 u1, float2 u2, float2 u3) {
  float2 r0, r1;
  r0.x = u0.x * a0.x - u0.y * a0.y + u1.x * a1.x - u1.y * a1.y;
  r0.y = u0.x * a0.y + u0.y * a0.x + u1.x * a1.y + u1.y * a1.x;
  r1.x = u2.x * a0.x - u2.y * a0.y + u3.x * a1.x - u3.y * a1.y;
  r1.y = u2.x * a0.y + u2.y * a0.x + u3.x * a1.y + u3.y * a1.x;
  a0 = r0; a1 = r1;
}

// Rotation on register-local bit BIT of a 32-amp subcube.
template<int BIT>
__device__ __forceinline__ void rotg32(float2* a, const float2* su) {
  float2 u0 = su[0], u1 = su[1], u2 = su[2], u3 = su[3];
#pragma unroll
  for (int j = 0; j < 32; j++) {
    if (((j >> BIT) & 1) == 0) {
      crot(a[j], a[j | (1 << BIT)], u0, u1, u2, u3);
    }
  }
}

// CNOT with control BC / target BT both register bits.
template<int BC, int BT>
__device__ __forceinline__ void cnotl32(float2* a) {
#pragma unroll
  for (int j = 0; j < 32; j++) {
    if (((j >> BC) & 1) == 1 && ((j >> BT) & 1) == 0) {
      int k = j | (1 << BT);
      float2 t = a[j]; a[j] = a[k]; a[k] = t;
    }
  }
}

// X on register bit BT conditioned on a runtime (thread-uniform) control bit.
template<int BT>
__device__ __forceinline__ void xcond32(float2* a, bool c) {
#pragma unroll
  for (int j = 0; j < 32; j++) {
    if (((j >> BT) & 1) == 0) {
      int k = j | (1 << BT);
      float2 t0 = a[j], t1 = a[k];
      a[j] = c ? t1 : t0;
      a[k] = c ? t0 : t1;
    }
  }
}

// Rotation on a lane-bit qubit (amp bit = lane bit LB).
template<int LB>
__device__ __forceinline__ void rot_lane(float2* a, const float2* su, int lane) {
  float2 u0 = su[0], u1 = su[1], u2 = su[2], u3 = su[3];
  const int c = (lane >> LB) & 1;
  float2 ua = c ? u3 : u0;   // coefficient on own amp
  float2 ub = c ? u2 : u1;   // coefficient on partner amp
#pragma unroll
  for (int j = 0; j < 32; j++) {
    float px = __shfl_xor_sync(0xffffffffu, a[j].x, 1 << LB);
    float py = __shfl_xor_sync(0xffffffffu, a[j].y, 1 << LB);
    float2 o = a[j];
    a[j].x = ua.x * o.x - ua.y * o.y + ub.x * px - ub.y * py;
    a[j].y = ua.x * o.y + ua.y * o.x + ub.x * py + ub.y * px;
  }
}

// Amp index convention: qubit q <-> bit (14 - q). Class = amp bits 14..13.
__global__ void __launch_bounds__(NTHREADS, 1) __cluster_dims__(2, 1, 1)
qdarts_kernel(const float* __restrict__ x, const float* __restrict__ Pm,
              const float* __restrict__ Qm, const float* __restrict__ rotp,
              const float* __restrict__ gum, float* __restrict__ out)
{
  __shared__ float2 sU[N_LAYERS * N_QUBITS * 4];
  __shared__ float  sw[N_QUBITS][2];
  __shared__ float  sred[4];

  cg::cluster_group cluster = cg::this_cluster();
  const int tid  = threadIdx.x;
  const int b    = blockIdx.x >> 1;
  const int rank = blockIdx.x & 1;
  const int lane = tid & 31;
  const int wg   = (rank << 4) | (tid >> 5);   // global warp id 0..31

  // ---- Gate selection: argmax(P@Q + gumbel); build RX/RY/RZ(theta). ----
  if (tid < N_LAYERS * N_QUBITS) {
    const int idx = tid;
    float best = -1e30f; int gb = 0;
#pragma unroll
    for (int gg = 0; gg < 3; gg++) {
      float logit = 0.f;
#pragma unroll
      for (int k = 0; k < 4; k++)
        logit += Pm[idx * 4 + k] * Qm[(idx * 4 + k) * 3 + gg];
      float v = logit + gum[idx * 3 + gg];
      if (v > best) { best = v; gb = gg; }
    }
    float th = rotp[idx];
    float sv, cv;
    sincosf(0.5f * th, &sv, &cv);
    float2 u0, u1, u2, u3;
    if (gb == 0) {        // RX
      u0 = make_float2(cv, 0.f);   u1 = make_float2(0.f, -sv);
      u2 = make_float2(0.f, -sv);  u3 = make_float2(cv, 0.f);
    } else if (gb == 1) { // RY
      u0 = make_float2(cv, 0.f);   u1 = make_float2(-sv, 0.f);
      u2 = make_float2(sv, 0.f);   u3 = make_float2(cv, 0.f);
    } else {              // RZ
      u0 = make_float2(cv, -sv);   u1 = make_float2(0.f, 0.f);
      u2 = make_float2(0.f, 0.f);  u3 = make_float2(cv, sv);
    }
    sU[idx * 4 + 0] = u0; sU[idx * 4 + 1] = u1;
    sU[idx * 4 + 2] = u2; sU[idx * 4 + 3] = u3;
  }
  if (tid < N_QUBITS) {
    float xv = x[b * N_QUBITS + tid];
    float sv, cv;
    sincosf(0.5f * xv, &sv, &cv);
    sw[tid][0] = cv; sw[tid][1] = sv;
  }
  if (tid < 4) sred[tid] = 0.f;
  __syncthreads();

  // Composed lane permutation for CNOT chain (4,5)(5,6)(6,7)(7,8)(8,9):
  // src = p_{56}(p_{67}(p_{78}(p_{89}(lane)))); odd register j adds lane^16.
  int t_ = lane;
  t_ ^= ((t_ >> 1) & 1) << 0;   // C(8,9) (applied last)
  t_ ^= ((t_ >> 2) & 1) << 1;   // C(7,8)
  t_ ^= ((t_ >> 3) & 1) << 2;   // C(6,7)
  t_ ^= ((t_ >> 4) & 1) << 3;   // C(5,6) (applied first of the lane chain)
  const int src_even = t_;
  const int src_odd  = t_ ^ 16; // C(4,5): control reg bit0, target lane bit4

  float2* S = g_state + b * NSTATE;
  float ps0 = 0.f, ps1 = 0.f, ps2 = 0.f, ps3 = 0.f;

#pragma unroll 1
  for (int l = 0; l < N_LAYERS; l++) {
    const float2* UL = &sU[l * N_QUBITS * 4];

    // ======== Pass 1: amp = (j<<10)|(lane<<5)|wg ========
    // reg j bits 4..0 = qubits 0..4; lane bits 4..0 = qubits 5..9; wg = q10..14.
    {
      float2 a[32];
      if (l == 0) {
        float pref = 1.f;
#pragma unroll
        for (int q = 5; q < 10; q++)  pref *= sw[q][(lane >> (9 - q)) & 1];
#pragma unroll
        for (int q = 10; q < 15; q++) pref *= sw[q][(wg >> (14 - q)) & 1];
#pragma unroll
        for (int j = 0; j < 32; j++) {
          float v = pref;
#pragma unroll
          for (int q = 0; q < 5; q++) v *= sw[q][(j >> (4 - q)) & 1];
          a[j] = make_float2(v, 0.f);
        }
      } else {
#pragma unroll
        for (int j = 0; j < 32; j++) a[j] = S[(j << 10) | (lane << 5) | wg];
        xcond32<4>(a, (wg & 1) != 0);   // deferred CNOT(14,0) of layer l-1
      }
      // Rotations q0..q4 (register bits 4..0)
      rotg32<4>(a, UL + 0 * 4);
      rotg32<3>(a, UL + 1 * 4);
      rotg32<2>(a, UL + 2 * 4);
      rotg32<1>(a, UL + 3 * 4);
      rotg32<0>(a, UL + 4 * 4);
      // Rotations q5..q9 (lane bits 4..0)
      rot_lane<4>(a, UL + 5 * 4, lane);
      rot_lane<3>(a, UL + 6 * 4, lane);
      rot_lane<2>(a, UL + 7 * 4, lane);
      rot_lane<1>(a, UL + 8 * 4, lane);
      rot_lane<0>(a, UL + 9 * 4, lane);
      // CNOT(0,1),(1,2),(2,3),(3,4): register
      cnotl32<4, 3>(a);
      cnotl32<3, 2>(a);
      cnotl32<2, 1>(a);
      cnotl32<1, 0>(a);
      // CNOT(4,5)+(5,6)+(6,7)+(7,8)+(8,9): one composed lane permutation.
#pragma unroll
      for (int j = 0; j < 32; j++) {
        const int src = (j & 1) ? src_odd : src_even;
        a[j].x = __shfl_sync(0xffffffffu, a[j].x, src);
        a[j].y = __shfl_sync(0xffffffffu, a[j].y, src);
      }
      // CNOT(9,10) deferred to pass 2 (its target q10 is a wg bit here).
#pragma unroll
      for (int j = 0; j < 32; j++) S[(j << 10) | (lane << 5) | wg] = a[j];
    }
    cluster.sync();

    // ======== Pass 2: amp = (wg<<10)|(lane<<5)|j ========
    // reg j bits 4..0 = qubits 10..14; lane bits = q5..9; wg bits = q0..4.
    {
      const int base = (wg << 10) | (lane << 5);
      float2 a[32];
      const float4* pv = (const float4*)(S + base);
#pragma unroll
      for (int j2 = 0; j2 < 16; j2++) {
        float4 v = pv[j2];
        a[2 * j2]     = make_float2(v.x, v.y);
        a[2 * j2 + 1] = make_float2(v.z, v.w);
      }
      // Rotations q10..q14 (register bits 4..0)
      rotg32<4>(a, UL + 10 * 4);
      rotg32<3>(a, UL + 11 * 4);
      rotg32<2>(a, UL + 12 * 4);
      rotg32<1>(a, UL + 13 * 4);
      rotg32<0>(a, UL + 14 * 4);
      // CNOT(9,10): control q9 = amp bit5 = lane bit0; target q10 = reg bit4.
      xcond32<4>(a, (lane & 1) != 0);
      // CNOT(10,11),(11,12),(12,13),(13,14): register
      cnotl32<4, 3>(a);
      cnotl32<3, 2>(a);
      cnotl32<2, 1>(a);
      cnotl32<1, 0>(a);

      if (l < N_LAYERS - 1) {
        float4* pw = (float4*)(S + base);
#pragma unroll
        for (int j2 = 0; j2 < 16; j2++) {
          pw[j2] = make_float4(a[2 * j2].x, a[2 * j2].y,
                               a[2 * j2 + 1].x, a[2 * j2 + 1].y);
        }
      } else {
        // Fold CNOT(14,0) + |amp|^2 class reduction.
        // class = amp bits 14..13 = wg bits 4..3; control q14 = amp bit0 = j&1.
        float pe = 0.f, po = 0.f;
#pragma unroll
        for (int j = 0; j < 32; j++) {
          float p = a[j].x * a[j].x + a[j].y * a[j].y;
          if (j & 1) po += p; else pe += p;
        }
        const int c = (wg >> 3) & 3;
        if      (c == 0) { ps0 = pe; ps2 = po; }
        else if (c == 1) { ps1 = pe; ps3 = po; }
        else if (c == 2) { ps2 = pe; ps0 = po; }
        else             { ps3 = pe; ps1 = po; }
      }
    }
    if (l < N_LAYERS - 1) cluster.sync();
  }

  // ---- Reduce class sums: warp -> CTA shared -> cross-CTA (DSMEM) ----
#pragma unroll
  for (int o = 16; o > 0; o >>= 1) {
    ps0 += __shfl_xor_sync(0xffffffffu, ps0, o);
    ps1 += __shfl_xor_sync(0xffffffffu, ps1, o);
    ps2 += __shfl_xor_sync(0xffffffffu, ps2, o);
    ps3 += __shfl_xor_sync(0xffffffffu, ps3, o);
  }
  if ((tid & 31) == 0) {
    atomicAdd(&sred[0], ps0);
    atomicAdd(&sred[1], ps1);
    atomicAdd(&sred[2], ps2);
    atomicAdd(&sred[3], ps3);
  }
  __syncthreads();

  if (rank == 1 && tid < 4) {
    float* dst = cluster.map_shared_rank(sred, 0);
    atomicAdd(dst + tid, sred[tid]);
  }
  cluster.sync();
  if (rank == 0 && tid < 4) out[b * 4 + tid] = sred[tid];
}

extern "C" void kernel_launch(void* const* d_in, const int* in_sizes, int n_in,
                              void* d_out, int out_size) {
  const float* x    = (const float*)d_in[0];
  const float* P    = (const float*)d_in[1];
  const float* Q    = (const float*)d_in[2];
  const float* rotp = (const float*)d_in[3];
  const float* gum  = (const float*)d_in[4];
  qdarts_kernel<<<BATCHN * 2, NTHREADS>>>(x, P, Q, rotp, gum, (float*)d_out);
}

// round 6
// speedup vs baseline: 2.0696x; 2.0696x over previous
#include <cuda_runtime.h>
#include <cooperative_groups.h>

namespace cg = cooperative_groups;

#define N_QUBITS 15
#define N_LAYERS 4
#define BATCHN   64
#define NSTATE   (1 << N_QUBITS)   // 32768
#define NTHREADS 512

// 16 MB L2-resident state scratch: [batch][32768] complex64 as float2.
__device__ float2 g_state[BATCHN * NSTATE];

__device__ __forceinline__ void crot(float2& a0, float2& a1,
                                     float2 u0, float2 u1, float2 u2, float2 u3) {
  float2 r0, r1;
  r0.x = u0.x * a0.x - u0.y * a0.y + u1.x * a1.x - u1.y * a1.y;
  r0.y = u0.x * a0.y + u0.y * a0.x + u1.x * a1.y + u1.y * a1.x;
  r1.x = u2.x * a0.x - u2.y * a0.y + u3.x * a1.x - u3.y * a1.y;
  r1.y = u2.x * a0.y + u2.y * a0.x + u3.x * a1.y + u3.y * a1.x;
  a0 = r0; a1 = r1;
}

// Rotation on register-local bit BIT of a 32-amp subcube.
template<int BIT>
__device__ __forceinline__ void rotg32(float2* a, const float2* su) {
  float2 u0 = su[0], u1 = su[1], u2 = su[2], u3 = su[3];
#pragma unroll
  for (int j = 0; j < 32; j++) {
    if (((j >> BIT) & 1) == 0) {
      crot(a[j], a[j | (1 << BIT)], u0, u1, u2, u3);
    }
  }
}

// CNOT with control BC / target BT both register bits.
template<int BC, int BT>
__device__ __forceinline__ void cnotl32(float2* a) {
#pragma unroll
  for (int j = 0; j < 32; j++) {
    if (((j >> BC) & 1) == 1 && ((j >> BT) & 1) == 0) {
      int k = j | (1 << BT);
      float2 t = a[j]; a[j] = a[k]; a[k] = t;
    }
  }
}

// X on register bit BT conditioned on a runtime (thread-uniform) control bit.
template<int BT>
__device__ __forceinline__ void xcond32(float2* a, bool c) {
#pragma unroll
  for (int j = 0; j < 32; j++) {
    if (((j >> BT) & 1) == 0) {
      int k = j | (1 << BT);
      float2 t0 = a[j], t1 = a[k];
      a[j] = c ? t1 : t0;
      a[k] = c ? t0 : t1;
    }
  }
}

// Rotation on a lane-bit qubit (amp bit = lane bit LB).
template<int LB>
__device__ __forceinline__ void rot_lane(float2* a, const float2* su, int lane) {
  float2 u0 = su[0], u1 = su[1], u2 = su[2], u3 = su[3];
  const int c = (lane >> LB) & 1;
  float2 ua = c ? u3 : u0;   // coefficient on own amp
  float2 ub = c ? u2 : u1;   // coefficient on partner amp
#pragma unroll
  for (int j = 0; j < 32; j++) {
    float px = __shfl_xor_sync(0xffffffffu, a[j].x, 1 << LB);
    float py = __shfl_xor_sync(0xffffffffu, a[j].y, 1 << LB);
    float2 o = a[j];
    a[j].x = ua.x * o.x - ua.y * o.y + ub.x * px - ub.y * py;
    a[j].y = ua.x * o.y + ua.y * o.x + ub.x * py + ub.y * px;
  }
}

// Amp index convention: qubit q <-> bit (14 - q). Class = amp bits 14..13.
__global__ void __launch_bounds__(NTHREADS, 1) __cluster_dims__(2, 1, 1)
qdarts_kernel(const float* __restrict__ x, const float* __restrict__ Pm,
              const float* __restrict__ Qm, const float* __restrict__ rotp,
              const float* __restrict__ gum, float* __restrict__ out)
{
  __shared__ float2 sU[N_LAYERS * N_QUBITS * 4];
  __shared__ float  sw[N_QUBITS][2];
  __shared__ float  sred[4];

  cg::cluster_group cluster = cg::this_cluster();
  const int tid  = threadIdx.x;
  const int b    = blockIdx.x >> 1;
  const int rank = blockIdx.x & 1;
  const int lane = tid & 31;
  const int idx  = (rank << 9) | tid;          // pass-1 index: amp bits 9..0
  const int wg   = (rank << 4) | (tid >> 5);   // pass-2 warp id: amp bits 14..10

  // ---- Gate selection: argmax(P@Q + gumbel); build RX/RY/RZ(theta). ----
  if (tid < N_LAYERS * N_QUBITS) {
    const int ix = tid;
    float best = -1e30f; int gb = 0;
#pragma unroll
    for (int gg = 0; gg < 3; gg++) {
      float logit = 0.f;
#pragma unroll
      for (int k = 0; k < 4; k++)
        logit += Pm[ix * 4 + k] * Qm[(ix * 4 + k) * 3 + gg];
      float v = logit + gum[ix * 3 + gg];
      if (v > best) { best = v; gb = gg; }
    }
    float th = rotp[ix];
    float sv, cv;
    sincosf(0.5f * th, &sv, &cv);
    float2 u0, u1, u2, u3;
    if (gb == 0) {        // RX
      u0 = make_float2(cv, 0.f);   u1 = make_float2(0.f, -sv);
      u2 = make_float2(0.f, -sv);  u3 = make_float2(cv, 0.f);
    } else if (gb == 1) { // RY
      u0 = make_float2(cv, 0.f);   u1 = make_float2(-sv, 0.f);
      u2 = make_float2(sv, 0.f);   u3 = make_float2(cv, 0.f);
    } else {              // RZ
      u0 = make_float2(cv, -sv);   u1 = make_float2(0.f, 0.f);
      u2 = make_float2(0.f, 0.f);  u3 = make_float2(cv, sv);
    }
    sU[ix * 4 + 0] = u0; sU[ix * 4 + 1] = u1;
    sU[ix * 4 + 2] = u2; sU[ix * 4 + 3] = u3;
  }
  if (tid < N_QUBITS) {
    float xv = x[b * N_QUBITS + tid];
    float sv, cv;
    sincosf(0.5f * xv, &sv, &cv);
    sw[tid][0] = cv; sw[tid][1] = sv;
  }
  if (tid < 4) sred[tid] = 0.f;
  __syncthreads();

  // Composed lane permutation for CNOT chain (10,11)(11,12)(12,13)(13,14):
  // lane bits 4..0 = amp bits 4..0 = qubits 10..14.
  // src = G_{10,11}(G_{11,12}(G_{12,13}(G_{13,14}(lane)))).
  int t_ = lane;
  t_ ^= ((t_ >> 1) & 1) << 0;   // C(13,14) (applied first to src calc)
  t_ ^= ((t_ >> 2) & 1) << 1;   // C(12,13)
  t_ ^= ((t_ >> 3) & 1) << 2;   // C(11,12)
  t_ ^= ((t_ >> 4) & 1) << 3;   // C(10,11)
  const int src_even = t_;
  const int src_odd  = t_ ^ 16; // C(9,10): control reg bit0 (odd j), target lane bit4

  float2* S = g_state + b * NSTATE;
  float ps0 = 0.f, ps1 = 0.f, ps2 = 0.f, ps3 = 0.f;

#pragma unroll 1
  for (int l = 0; l < N_LAYERS; l++) {
    const float2* UL = &sU[l * N_QUBITS * 4];

    // ======== Pass 1: amp = (j<<10)|idx.  reg j = amp bits 14..10 (q0..q4) ====
    {
      float2 a[32];
      if (l == 0) {
        float pref = 1.f;
#pragma unroll
        for (int q = 5; q < 15; q++) pref *= sw[q][(idx >> (14 - q)) & 1];
#pragma unroll
        for (int j = 0; j < 32; j++) {
          float v = pref;
#pragma unroll
          for (int q = 0; q < 5; q++) v *= sw[q][(j >> (4 - q)) & 1];
          a[j] = make_float2(v, 0.f);
        }
      } else {
#pragma unroll
        for (int j = 0; j < 32; j++) a[j] = S[(j << 10) | idx];
        xcond32<4>(a, (idx & 1) != 0);  // deferred CNOT(14,0) of layer l-1
      }
      rotg32<4>(a, UL + 0 * 4);   // R_q0
      rotg32<3>(a, UL + 1 * 4);   // R_q1
      rotg32<2>(a, UL + 2 * 4);   // R_q2
      rotg32<1>(a, UL + 3 * 4);   // R_q3
      rotg32<0>(a, UL + 4 * 4);   // R_q4
      cnotl32<4, 3>(a);           // CNOT(0,1)
      cnotl32<3, 2>(a);           // CNOT(1,2)
      cnotl32<2, 1>(a);           // CNOT(2,3)
      cnotl32<1, 0>(a);           // CNOT(3,4)
      // CNOT(4,5) deferred to pass 2 (target q5 not local here).
#pragma unroll
      for (int j = 0; j < 32; j++) S[(j << 10) | idx] = a[j];
    }
    cluster.sync();

    // ======== Pass 2: amp = (wg<<10)|(j<<5)|lane ========
    // reg j = amp bits 9..5 (q5..q9); lane = amp bits 4..0 (q10..q14).
    {
      const int base = (wg << 10) | lane;
      float2 a[32];
#pragma unroll
      for (int j = 0; j < 32; j++) a[j] = S[base | (j << 5)];
      // Rotations q5..q9 (register bits 4..0)
      rotg32<4>(a, UL + 5 * 4);
      rotg32<3>(a, UL + 6 * 4);
      rotg32<2>(a, UL + 7 * 4);
      rotg32<1>(a, UL + 8 * 4);
      rotg32<0>(a, UL + 9 * 4);
      // Rotations q10..q14 (lane bits 4..0)
      rot_lane<4>(a, UL + 10 * 4, lane);
      rot_lane<3>(a, UL + 11 * 4, lane);
      rot_lane<2>(a, UL + 12 * 4, lane);
      rot_lane<1>(a, UL + 13 * 4, lane);
      rot_lane<0>(a, UL + 14 * 4, lane);
      // CNOT(4,5): control q4 = amp bit10 = wg bit0; target q5 = reg bit4.
      xcond32<4>(a, (wg & 1) != 0);
      // CNOT(5,6),(6,7),(7,8),(8,9): register.
      cnotl32<4, 3>(a);
      cnotl32<3, 2>(a);
      cnotl32<2, 1>(a);
      cnotl32<1, 0>(a);
      // CNOT(9,10) + chain (10,11)..(13,14): one composed lane permutation.
#pragma unroll
      for (int j = 0; j < 32; j++) {
        const int src = (j & 1) ? src_odd : src_even;
        a[j].x = __shfl_sync(0xffffffffu, a[j].x, src);
        a[j].y = __shfl_sync(0xffffffffu, a[j].y, src);
      }
      // CNOT(14,0) deferred (target q0 not local): next pass 1, or folded below.

      if (l < N_LAYERS - 1) {
#pragma unroll
        for (int j = 0; j < 32; j++) S[base | (j << 5)] = a[j];
      } else {
        // Fold CNOT(14,0) + |amp|^2 class reduction.
        // class = amp bits 14..13 = wg bits 4..3; control q14 = amp bit0 = lane bit0.
        float p = 0.f;
#pragma unroll
        for (int j = 0; j < 32; j++)
          p += a[j].x * a[j].x + a[j].y * a[j].y;
        int c = (wg >> 3) & 3;
        if (lane & 1) c ^= 2;
        if      (c == 0) ps0 = p;
        else if (c == 1) ps1 = p;
        else if (c == 2) ps2 = p;
        else             ps3 = p;
      }
    }
    if (l < N_LAYERS - 1) cluster.sync();
  }

  // ---- Reduce class sums: warp -> CTA shared -> cross-CTA (DSMEM) ----
#pragma unroll
  for (int o = 16; o > 0; o >>= 1) {
    ps0 += __shfl_xor_sync(0xffffffffu, ps0, o);
    ps1 += __shfl_xor_sync(0xffffffffu, ps1, o);
    ps2 += __shfl_xor_sync(0xffffffffu, ps2, o);
    ps3 += __shfl_xor_sync(0xffffffffu, ps3, o);
  }
  if ((tid & 31) == 0) {
    atomicAdd(&sred[0], ps0);
    atomicAdd(&sred[1], ps1);
    atomicAdd(&sred[2], ps2);
    atomicAdd(&sred[3], ps3);
  }
  __syncthreads();

  if (rank == 1 && tid < 4) {
    float* dst = cluster.map_shared_rank(sred, 0);
    atomicAdd(dst + tid, sred[tid]);
  }
  cluster.sync();
  if (rank == 0 && tid < 4) out[b * 4 + tid] = sred[tid];
}

extern "C" void kernel_launch(void* const* d_in, const int* in_sizes, int n_in,
                              void* d_out, int out_size) {
  const float* x    = (const float*)d_in[0];
  const float* P    = (const float*)d_in[1];
  const float* Q    = (const float*)d_in[2];
  const float* rotp = (const float*)d_in[3];
  const float* gum  = (const float*)d_in[4];
  qdarts_kernel<<<BATCHN * 2, NTHREADS>>>(x, P, Q, rotp, gum, (float*)d_out);
}

// round 7
// speedup vs baseline: 2.2766x; 1.1000x over previous
#include <cuda_runtime.h>
#include <cooperative_groups.h>

namespace cg = cooperative_groups;

#define N_QUBITS 15
#define N_LAYERS 4
#define BATCHN   64
#define NSTATE   (1 << N_QUBITS)   // 32768
#define NTHREADS 512

// 16 MB L2-resident state scratch: [batch][32768] complex64 as float2.
__device__ float2 g_state[BATCHN * NSTATE];

// ---------------------------------------------------------------------------
// Specialized rotation on register-local bit BIT of a 32-amp subcube.
// Gate types: 0=RX, 1=RY, 2=RZ. Branches are uniform across the block.
//   RX: a0' = c a0 + s J(a1),  a1' = c a1 + s J(a0)      (J(v) = (v.y, -v.x))
//   RY: a0' = c a0 - s a1,     a1' = c a1 + s a0
//   RZ: a' = (c -/+ i s) a  (diagonal; same J-form with operand = self)
// RX and RZ share one loop (operand select = uniform FSEL on ALU pipe).
// 8 fma-pipe ops per butterfly (vs 16 generic).
// ---------------------------------------------------------------------------
template<int BIT>
__device__ __forceinline__ void rotg32t(float2* a, float c, float s, int type) {
  if (type == 1) {  // RY (pure real butterfly)
#pragma unroll
    for (int j = 0; j < 32; j++) {
      if (((j >> BIT) & 1) == 0) {
        const int k = j | (1 << BIT);
        float2 A0 = a[j], A1 = a[k];
        a[j].x = fmaf(-s, A1.x, c * A0.x);
        a[j].y = fmaf(-s, A1.y, c * A0.y);
        a[k].x = fmaf( s, A0.x, c * A1.x);
        a[k].y = fmaf( s, A0.y, c * A1.y);
      }
    }
  } else {          // RX (partner operand) / RZ (self operand)
    const bool isRZ = (type == 2);
    const float s_hi = isRZ ? -s : s;
#pragma unroll
    for (int j = 0; j < 32; j++) {
      if (((j >> BIT) & 1) == 0) {
        const int k = j | (1 << BIT);
        float2 A0 = a[j], A1 = a[k];
        float2 oL = isRZ ? A0 : A1;   // uniform FSEL (ALU pipe)
        float2 oH = isRZ ? A1 : A0;
        a[j].x = fmaf( s,    oL.y, c * A0.x);
        a[j].y = fmaf(-s,    oL.x, c * A0.y);
        a[k].x = fmaf( s_hi, oH.y, c * A1.x);
        a[k].y = fmaf(-s_hi, oH.x, c * A1.y);
      }
    }
  }
}

// Specialized rotation on a lane-bit qubit (amp bit = lane bit LB).
template<int LB>
__device__ __forceinline__ void rot_lane_t(float2* a, float c, float s,
                                           int type, int lane) {
  const int cb = (lane >> LB) & 1;
  if (type == 2) {  // RZ: diagonal, NO shuffles
    const float sg = cb ? -s : s;
#pragma unroll
    for (int j = 0; j < 32; j++) {
      float nx = fmaf( sg, a[j].y, c * a[j].x);
      float ny = fmaf(-sg, a[j].x, c * a[j].y);
      a[j].x = nx; a[j].y = ny;
    }
  } else if (type == 0) {  // RX: r = c*o + s*J(p), same formula both halves
#pragma unroll
    for (int j = 0; j < 32; j++) {
      float px = __shfl_xor_sync(0xffffffffu, a[j].x, 1 << LB);
      float py = __shfl_xor_sync(0xffffffffu, a[j].y, 1 << LB);
      float nx = fmaf( s, py, c * a[j].x);
      float ny = fmaf(-s, px, c * a[j].y);
      a[j].x = nx; a[j].y = ny;
    }
  } else {  // RY: r = c*o + sg*p, sg = +s for upper half, -s for lower
    const float sg = cb ? s : -s;
#pragma unroll
    for (int j = 0; j < 32; j++) {
      float px = __shfl_xor_sync(0xffffffffu, a[j].x, 1 << LB);
      float py = __shfl_xor_sync(0xffffffffu, a[j].y, 1 << LB);
      a[j].x = fmaf(sg, px, c * a[j].x);
      a[j].y = fmaf(sg, py, c * a[j].y);
    }
  }
}

// CNOT with control BC / target BT both register bits (free after copy-prop).
template<int BC, int BT>
__device__ __forceinline__ void cnotl32(float2* a) {
#pragma unroll
  for (int j = 0; j < 32; j++) {
    if (((j >> BC) & 1) == 1 && ((j >> BT) & 1) == 0) {
      int k = j | (1 << BT);
      float2 t = a[j]; a[j] = a[k]; a[k] = t;
    }
  }
}

// X on register bit BT conditioned on a runtime (thread-uniform) control bit.
template<int BT>
__device__ __forceinline__ void xcond32(float2* a, bool c) {
#pragma unroll
  for (int j = 0; j < 32; j++) {
    if (((j >> BT) & 1) == 0) {
      int k = j | (1 << BT);
      float2 t0 = a[j], t1 = a[k];
      a[j] = c ? t1 : t0;
      a[k] = c ? t0 : t1;
    }
  }
}

// Amp index convention: qubit q <-> bit (14 - q). Class = amp bits 14..13.
__global__ void __launch_bounds__(NTHREADS, 1) __cluster_dims__(2, 1, 1)
qdarts_kernel(const float* __restrict__ x, const float* __restrict__ Pm,
              const float* __restrict__ Qm, const float* __restrict__ rotp,
              const float* __restrict__ gum, float* __restrict__ out)
{
  __shared__ float sc[N_LAYERS * N_QUBITS];   // cos(theta/2) per gate
  __shared__ float ss[N_LAYERS * N_QUBITS];   // sin(theta/2) per gate
  __shared__ int   sty[N_LAYERS * N_QUBITS];  // selected gate type 0/1/2
  __shared__ float sw[N_QUBITS][2];           // encoding cos/sin per qubit
  __shared__ float sred[4];

  cg::cluster_group cluster = cg::this_cluster();
  const int tid  = threadIdx.x;
  const int b    = blockIdx.x >> 1;
  const int rank = blockIdx.x & 1;
  const int lane = tid & 31;
  const int idx  = (rank << 9) | tid;          // pass-1 index: amp bits 9..0
  const int wg   = (rank << 4) | (tid >> 5);   // pass-2 warp id: amp bits 14..10

  // ---- Gate selection: argmax(P@Q + gumbel); store (c, s, type). ----
  if (tid < N_LAYERS * N_QUBITS) {
    const int ix = tid;
    float best = -1e30f; int gb = 0;
#pragma unroll
    for (int gg = 0; gg < 3; gg++) {
      float logit = 0.f;
#pragma unroll
      for (int k = 0; k < 4; k++)
        logit += Pm[ix * 4 + k] * Qm[(ix * 4 + k) * 3 + gg];
      float v = logit + gum[ix * 3 + gg];
      if (v > best) { best = v; gb = gg; }
    }
    float sv, cv;
    sincosf(0.5f * rotp[ix], &sv, &cv);
    sc[ix] = cv; ss[ix] = sv; sty[ix] = gb;
  }
  if (tid < N_QUBITS) {
    float sv, cv;
    sincosf(0.5f * x[b * N_QUBITS + tid], &sv, &cv);
    sw[tid][0] = cv; sw[tid][1] = sv;
  }
  if (tid < 4) sred[tid] = 0.f;
  __syncthreads();

  // Composed lane permutation for CNOT chain (10,11)(11,12)(12,13)(13,14):
  // lane bits 4..0 = amp bits 4..0 = qubits 10..14.
  int t_ = lane;
  t_ ^= ((t_ >> 1) & 1) << 0;   // C(13,14)
  t_ ^= ((t_ >> 2) & 1) << 1;   // C(12,13)
  t_ ^= ((t_ >> 3) & 1) << 2;   // C(11,12)
  t_ ^= ((t_ >> 4) & 1) << 3;   // C(10,11)
  const int src_even = t_;
  const int src_odd  = t_ ^ 16; // C(9,10): control reg bit0 (odd j), target lane bit4

  float2* S = g_state + b * NSTATE;
  float ps0 = 0.f, ps1 = 0.f, ps2 = 0.f, ps3 = 0.f;

#pragma unroll 1
  for (int l = 0; l < N_LAYERS; l++) {
    const int g0 = l * N_QUBITS;

    // ======== Pass 1: amp = (j<<10)|idx.  reg j = amp bits 14..10 (q0..q4) ====
    {
      float2 a[32];
      if (l == 0) {
        float pref = 1.f;
#pragma unroll
        for (int q = 5; q < 15; q++) pref *= sw[q][(idx >> (14 - q)) & 1];
#pragma unroll
        for (int j = 0; j < 32; j++) {
          float v = pref;
#pragma unroll
          for (int q = 0; q < 5; q++) v *= sw[q][(j >> (4 - q)) & 1];
          a[j] = make_float2(v, 0.f);
        }
      } else {
#pragma unroll
        for (int j = 0; j < 32; j++) a[j] = S[(j << 10) | idx];
        xcond32<4>(a, (idx & 1) != 0);  // deferred CNOT(14,0) of layer l-1
      }
      rotg32t<4>(a, sc[g0 + 0], ss[g0 + 0], sty[g0 + 0]);   // R_q0
      rotg32t<3>(a, sc[g0 + 1], ss[g0 + 1], sty[g0 + 1]);   // R_q1
      rotg32t<2>(a, sc[g0 + 2], ss[g0 + 2], sty[g0 + 2]);   // R_q2
      rotg32t<1>(a, sc[g0 + 3], ss[g0 + 3], sty[g0 + 3]);   // R_q3
      rotg32t<0>(a, sc[g0 + 4], ss[g0 + 4], sty[g0 + 4]);   // R_q4
      cnotl32<4, 3>(a);           // CNOT(0,1)
      cnotl32<3, 2>(a);           // CNOT(1,2)
      cnotl32<2, 1>(a);           // CNOT(2,3)
      cnotl32<1, 0>(a);           // CNOT(3,4)
      // CNOT(4,5) deferred to pass 2.
#pragma unroll
      for (int j = 0; j < 32; j++) S[(j << 10) | idx] = a[j];
    }
    cluster.sync();

    // ======== Pass 2: amp = (wg<<10)|(j<<5)|lane ========
    // reg j = amp bits 9..5 (q5..q9); lane = amp bits 4..0 (q10..q14).
    {
      const int base = (wg << 10) | lane;
      float2 a[32];
#pragma unroll
      for (int j = 0; j < 32; j++) a[j] = S[base | (j << 5)];
      // Rotations q5..q9 (register bits 4..0)
      rotg32t<4>(a, sc[g0 + 5], ss[g0 + 5], sty[g0 + 5]);
      rotg32t<3>(a, sc[g0 + 6], ss[g0 + 6], sty[g0 + 6]);
      rotg32t<2>(a, sc[g0 + 7], ss[g0 + 7], sty[g0 + 7]);
      rotg32t<1>(a, sc[g0 + 8], ss[g0 + 8], sty[g0 + 8]);
      rotg32t<0>(a, sc[g0 + 9], ss[g0 + 9], sty[g0 + 9]);
      // Rotations q10..q14 (lane bits 4..0)
      rot_lane_t<4>(a, sc[g0 + 10], ss[g0 + 10], sty[g0 + 10], lane);
      rot_lane_t<3>(a, sc[g0 + 11], ss[g0 + 11], sty[g0 + 11], lane);
      rot_lane_t<2>(a, sc[g0 + 12], ss[g0 + 12], sty[g0 + 12], lane);
      rot_lane_t<1>(a, sc[g0 + 13], ss[g0 + 13], sty[g0 + 13], lane);
      rot_lane_t<0>(a, sc[g0 + 14], ss[g0 + 14], sty[g0 + 14], lane);
      // CNOT(4,5): control q4 = amp bit10 = wg bit0; target q5 = reg bit4.
      xcond32<4>(a, (wg & 1) != 0);
      // CNOT(5,6),(6,7),(7,8),(8,9): register.
      cnotl32<4, 3>(a);
      cnotl32<3, 2>(a);
      cnotl32<2, 1>(a);
      cnotl32<1, 0>(a);
      // CNOT(9,10) + chain (10,11)..(13,14): one composed lane permutation.
#pragma unroll
      for (int j = 0; j < 32; j++) {
        const int src = (j & 1) ? src_odd : src_even;
        a[j].x = __shfl_sync(0xffffffffu, a[j].x, src);
        a[j].y = __shfl_sync(0xffffffffu, a[j].y, src);
      }
      // CNOT(14,0) deferred (next pass 1, or folded into the reduction).

      if (l < N_LAYERS - 1) {
#pragma unroll
        for (int j = 0; j < 32; j++) S[base | (j << 5)] = a[j];
      } else {
        // Fold CNOT(14,0) + |amp|^2 class reduction.
        // class = amp bits 14..13 = wg bits 4..3; control q14 = amp bit0 = lane bit0.
        float p = 0.f;
#pragma unroll
        for (int j = 0; j < 32; j++)
          p = fmaf(a[j].x, a[j].x, fmaf(a[j].y, a[j].y, p));
        int c = (wg >> 3) & 3;
        if (lane & 1) c ^= 2;
        if      (c == 0) ps0 = p;
        else if (c == 1) ps1 = p;
        else if (c == 2) ps2 = p;
        else             ps3 = p;
      }
    }
    if (l < N_LAYERS - 1) cluster.sync();
  }

  // ---- Reduce class sums: warp -> CTA shared -> cross-CTA (DSMEM) ----
#pragma unroll
  for (int o = 16; o > 0; o >>= 1) {
    ps0 += __shfl_xor_sync(0xffffffffu, ps0, o);
    ps1 += __shfl_xor_sync(0xffffffffu, ps1, o);
    ps2 += __shfl_xor_sync(0xffffffffu, ps2, o);
    ps3 += __shfl_xor_sync(0xffffffffu, ps3, o);
  }
  if ((tid & 31) == 0) {
    atomicAdd(&sred[0], ps0);
    atomicAdd(&sred[1], ps1);
    atomicAdd(&sred[2], ps2);
    atomicAdd(&sred[3], ps3);
  }
  __syncthreads();

  if (rank == 1 && tid < 4) {
    float* dst = cluster.map_shared_rank(sred, 0);
    atomicAdd(dst + tid, sred[tid]);
  }
  cluster.sync();
  if (rank == 0 && tid < 4) out[b * 4 + tid] = sred[tid];
}

extern "C" void kernel_launch(void* const* d_in, const int* in_sizes, int n_in,
                              void* d_out, int out_size) {
  const float* x    = (const float*)d_in[0];
  const float* P    = (const float*)d_in[1];
  const float* Q    = (const float*)d_in[2];
  const float* rotp = (const float*)d_in[3];
  const float* gum  = (const float*)d_in[4];
  qdarts_kernel<<<BATCHN * 2, NTHREADS>>>(x, P, Q, rotp, gum, (float*)d_out);
}

// round 8
// speedup vs baseline: 2.6110x; 1.1469x over previous
#include <cuda_runtime.h>
#include <cooperative_groups.h>

namespace cg = cooperative_groups;

#define N_QUBITS 15
#define N_LAYERS 4
#define BATCHN   64
#define NSTATE   (1 << N_QUBITS)   // 32768
#define NTHREADS 512
#define NWARPS   (NTHREADS / 32)
// Per-warp 32x33 float2 transpose pad: conflict-free STS.64/LDS.64.
#define TR_STRIDE 33
#define SMEM_BYTES (NWARPS * 32 * TR_STRIDE * sizeof(float2))

// 16 MB L2-resident state scratch: [batch][32768] complex64 as float2.
__device__ float2 g_state[BATCHN * NSTATE];

// ---------------------------------------------------------------------------
// Factored rotation on register bit BIT: gate = scale * (cheap matrix); the
// scale is accumulated globally and applied to the final probabilities.
// tf = type*2 + form:  type 0=RX 1=RY 2=RZ;  form 0: t=s/c (|c|>=|s|),
// form 1: t=c/s.  All variants: 2 fma-pipe ops per amplitude, no selects.
// ---------------------------------------------------------------------------
template<int BIT>
__device__ __forceinline__ void rotfac(float2* a, float t, int tf) {
  if (tf == 0) {          // RX /c: a0' = a0 + t J(a1); a1' = a1 + t J(a0)
#pragma unroll
    for (int j = 0; j < 32; j++) if (((j >> BIT) & 1) == 0) {
      const int k = j | (1 << BIT);
      float2 A0 = a[j], A1 = a[k];
      a[j].x = fmaf( t, A1.y, A0.x);  a[j].y = fmaf(-t, A1.x, A0.y);
      a[k].x = fmaf( t, A0.y, A1.x);  a[k].y = fmaf(-t, A0.x, A1.y);
    }
  } else if (tf == 1) {   // RX /s: a0' = u a0 + J(a1); a1' = u a1 + J(a0)
#pragma unroll
    for (int j = 0; j < 32; j++) if (((j >> BIT) & 1) == 0) {
      const int k = j | (1 << BIT);
      float2 A0 = a[j], A1 = a[k];
      a[j].x = fmaf(t, A0.x,  A1.y);  a[j].y = fmaf(t, A0.y, -A1.x);
      a[k].x = fmaf(t, A1.x,  A0.y);  a[k].y = fmaf(t, A1.y, -A0.x);
    }
  } else if (tf == 2) {   // RY /c: a0' = a0 - t a1; a1' = a1 + t a0
#pragma unroll
    for (int j = 0; j < 32; j++) if (((j >> BIT) & 1) == 0) {
      const int k = j | (1 << BIT);
      float2 A0 = a[j], A1 = a[k];
      a[j].x = fmaf(-t, A1.x, A0.x);  a[j].y = fmaf(-t, A1.y, A0.y);
      a[k].x = fmaf( t, A0.x, A1.x);  a[k].y = fmaf( t, A0.y, A1.y);
    }
  } else if (tf == 3) {   // RY /s: a0' = u a0 - a1; a1' = u a1 + a0
#pragma unroll
    for (int j = 0; j < 32; j++) if (((j >> BIT) & 1) == 0) {
      const int k = j | (1 << BIT);
      float2 A0 = a[j], A1 = a[k];
      a[j].x = fmaf(t, A0.x, -A1.x);  a[j].y = fmaf(t, A0.y, -A1.y);
      a[k].x = fmaf(t, A1.x,  A0.x);  a[k].y = fmaf(t, A1.y,  A0.y);
    }
  } else if (tf == 4) {   // RZ /c: bit0: (1-it)a; bit1: (1+it)a
#pragma unroll
    for (int j = 0; j < 32; j++) if (((j >> BIT) & 1) == 0) {
      const int k = j | (1 << BIT);
      float2 A0 = a[j], A1 = a[k];
      a[j].x = fmaf( t, A0.y, A0.x);  a[j].y = fmaf(-t, A0.x, A0.y);
      a[k].x = fmaf(-t, A1.y, A1.x);  a[k].y = fmaf( t, A1.x, A1.y);
    }
  } else {                // RZ /s: bit0: (u-i)a; bit1: (u+i)a
#pragma unroll
    for (int j = 0; j < 32; j++) if (((j >> BIT) & 1) == 0) {
      const int k = j | (1 << BIT);
      float2 A0 = a[j], A1 = a[k];
      a[j].x = fmaf(t, A0.x,  A0.y);  a[j].y = fmaf(t, A0.y, -A0.x);
      a[k].x = fmaf(t, A1.x, -A1.y);  a[k].y = fmaf(t, A1.y,  A1.x);
    }
  }
}

// CNOT with control BC / target BT both register bits (free register rename).
template<int BC, int BT>
__device__ __forceinline__ void cnotl32(float2* a) {
#pragma unroll
  for (int j = 0; j < 32; j++) {
    if (((j >> BC) & 1) == 1 && ((j >> BT) & 1) == 0) {
      int k = j | (1 << BT);
      float2 t = a[j]; a[j] = a[k]; a[k] = t;
    }
  }
}

// X on register bit BT conditioned on a (possibly divergent) control bit.
template<int BT>
__device__ __forceinline__ void xcond32(float2* a, bool c) {
#pragma unroll
  for (int j = 0; j < 32; j++) {
    if (((j >> BT) & 1) == 0) {
      int k = j | (1 << BT);
      float2 t0 = a[j], t1 = a[k];
      a[j] = c ? t1 : t0;
      a[k] = c ? t0 : t1;
    }
  }
}

// Amp index convention: qubit q <-> bit (14 - q). Class = amp bits 14..13.
__global__ void __launch_bounds__(NTHREADS, 1) __cluster_dims__(2, 1, 1)
qdarts_kernel(const float* __restrict__ x, const float* __restrict__ Pm,
              const float* __restrict__ Qm, const float* __restrict__ rotp,
              const float* __restrict__ gum, float* __restrict__ out)
{
  extern __shared__ float2 dsm[];   // NWARPS * 32 * TR_STRIDE float2

  __shared__ float st_t[N_LAYERS * N_QUBITS];   // per-gate ratio t (or u)
  __shared__ int   st_f[N_LAYERS * N_QUBITS];   // per-gate variant tf = type*2+form
  __shared__ float st_s[N_LAYERS * N_QUBITS];   // per-gate scale factor (c or s)
  __shared__ float sw[N_QUBITS][2];             // encoding cos/sin per qubit
  __shared__ float sred[4];
  __shared__ float sS2;                         // (prod scale)^2

  cg::cluster_group cluster = cg::this_cluster();
  const int tid  = threadIdx.x;
  const int b    = blockIdx.x >> 1;
  const int rank = blockIdx.x & 1;
  const int lane = tid & 31;
  const int w    = tid >> 5;                   // warp in CTA
  const int idx  = (rank << 9) | tid;          // pass-1 index: amp bits 9..0
  const int wg   = (rank << 4) | w;            // pass-2 warp id: amp bits 14..10

  // ---- Gate selection: argmax(P@Q + gumbel); store (t, variant, scale). ----
  if (tid < N_LAYERS * N_QUBITS) {
    const int ix = tid;
    float best = -1e30f; int gb = 0;
#pragma unroll
    for (int gg = 0; gg < 3; gg++) {
      float logit = 0.f;
#pragma unroll
      for (int k = 0; k < 4; k++)
        logit += Pm[ix * 4 + k] * Qm[(ix * 4 + k) * 3 + gg];
      float v = logit + gum[ix * 3 + gg];
      if (v > best) { best = v; gb = gg; }
    }
    float sv, cv;
    sincosf(0.5f * rotp[ix], &sv, &cv);
    const bool formB = fabsf(sv) > fabsf(cv);
    st_f[ix] = gb * 2 + (formB ? 1 : 0);
    st_t[ix] = formB ? __fdividef(cv, sv) : __fdividef(sv, cv);
    st_s[ix] = formB ? sv : cv;
  }
  if (tid < N_QUBITS) {
    float sv, cv;
    sincosf(0.5f * x[b * N_QUBITS + tid], &sv, &cv);
    sw[tid][0] = cv; sw[tid][1] = sv;
  }
  if (tid < 4) sred[tid] = 0.f;
  __syncthreads();

  if (tid == 0) {   // global scale product (others proceed; visible via later barriers)
    float pr = 1.f;
#pragma unroll 1
    for (int i = 0; i < N_LAYERS * N_QUBITS; i++) pr *= st_s[i];
    sS2 = pr * pr;
  }

  float2* S = g_state + b * NSTATE;
  float2* T = dsm + w * 32 * TR_STRIDE;   // this warp's transpose tile
  float ps0 = 0.f, ps1 = 0.f, ps2 = 0.f, ps3 = 0.f;

#pragma unroll 1
  for (int l = 0; l < N_LAYERS; l++) {
    const int g0 = l * N_QUBITS;

    // ======== Pass 1: amp = (j<<10)|idx.  reg j = amp bits 14..10 (q0..q4) ====
    {
      float2 a[32];
      if (l == 0) {
        float pref = 1.f;
#pragma unroll
        for (int q = 5; q < 15; q++) pref *= sw[q][(idx >> (14 - q)) & 1];
#pragma unroll
        for (int j = 0; j < 32; j++) {
          float v = pref;
#pragma unroll
          for (int q = 0; q < 5; q++) v *= sw[q][(j >> (4 - q)) & 1];
          a[j] = make_float2(v, 0.f);
        }
      } else {
#pragma unroll
        for (int j = 0; j < 32; j++) a[j] = S[(j << 10) | idx];
        xcond32<4>(a, (idx & 1) != 0);  // deferred CNOT(14,0) of layer l-1
      }
      rotfac<4>(a, st_t[g0 + 0], st_f[g0 + 0]);   // R_q0
      rotfac<3>(a, st_t[g0 + 1], st_f[g0 + 1]);   // R_q1
      rotfac<2>(a, st_t[g0 + 2], st_f[g0 + 2]);   // R_q2
      rotfac<1>(a, st_t[g0 + 3], st_f[g0 + 3]);   // R_q3
      rotfac<0>(a, st_t[g0 + 4], st_f[g0 + 4]);   // R_q4
      cnotl32<4, 3>(a);           // CNOT(0,1)
      cnotl32<3, 2>(a);           // CNOT(1,2)
      cnotl32<2, 1>(a);           // CNOT(2,3)
      cnotl32<1, 0>(a);           // CNOT(3,4)
      // CNOT(4,5) deferred to pass 2.
#pragma unroll
      for (int j = 0; j < 32; j++) S[(j << 10) | idx] = a[j];
    }
    cluster.sync();

    // ======== Pass 2: amp = (wg<<10)|(j<<5)|lane ========
    {
      const int base = (wg << 10) | lane;
      float2 a[32];
#pragma unroll
      for (int j = 0; j < 32; j++) a[j] = S[base | (j << 5)];
      // Rotations q5..q9 (register bits 4..0 = amp bits 9..5)
      rotfac<4>(a, st_t[g0 + 5], st_f[g0 + 5]);
      rotfac<3>(a, st_t[g0 + 6], st_f[g0 + 6]);
      rotfac<2>(a, st_t[g0 + 7], st_f[g0 + 7]);
      rotfac<1>(a, st_t[g0 + 8], st_f[g0 + 8]);
      rotfac<0>(a, st_t[g0 + 9], st_f[g0 + 9]);
      // CNOT(4,5): control q4 = wg bit0 (warp-uniform branch, free swap).
      if (wg & 1) {
#pragma unroll
        for (int j = 0; j < 16; j++) {   // swap reg bit4
          float2 t2 = a[j]; a[j] = a[j | 16]; a[j | 16] = t2;
        }
      }
      cnotl32<4, 3>(a);   // CNOT(5,6)
      cnotl32<3, 2>(a);   // CNOT(6,7)
      cnotl32<2, 1>(a);   // CNOT(7,8)
      cnotl32<1, 0>(a);   // CNOT(8,9)

      // --- Warp transpose: reg <-> lane (amp bits 9..5 <-> 4..0) ---
#pragma unroll
      for (int j = 0; j < 32; j++) T[lane * TR_STRIDE + j] = a[j];
      __syncwarp();
#pragma unroll
      for (int j = 0; j < 32; j++) a[j] = T[j * TR_STRIDE + lane];
      __syncwarp();
      // Now reg j = amp bits 4..0 (q10..q14); lane = amp bits 9..5 (q5..q9).

      // Rotations q10..q14 (register bits 4..0)
      rotfac<4>(a, st_t[g0 + 10], st_f[g0 + 10]);
      rotfac<3>(a, st_t[g0 + 11], st_f[g0 + 11]);
      rotfac<2>(a, st_t[g0 + 12], st_f[g0 + 12]);
      rotfac<1>(a, st_t[g0 + 13], st_f[g0 + 13]);
      rotfac<0>(a, st_t[g0 + 14], st_f[g0 + 14]);
      // CNOT(9,10): control q9 = amp bit5 = lane bit0; target q10 = reg bit4.
      xcond32<4>(a, (lane & 1) != 0);
      cnotl32<4, 3>(a);   // CNOT(10,11)
      cnotl32<3, 2>(a);   // CNOT(11,12)
      cnotl32<2, 1>(a);   // CNOT(12,13)
      cnotl32<1, 0>(a);   // CNOT(13,14)
      // CNOT(14,0) deferred (next pass 1, or folded into the reduction).

      if (l < N_LAYERS - 1) {
        // Transpose back and store coalesced.
#pragma unroll
        for (int j = 0; j < 32; j++) T[lane * TR_STRIDE + j] = a[j];
        __syncwarp();
#pragma unroll
        for (int j = 0; j < 32; j++) a[j] = T[j * TR_STRIDE + lane];
        __syncwarp();
#pragma unroll
        for (int j = 0; j < 32; j++) S[base | (j << 5)] = a[j];
      } else {
        // Fold CNOT(14,0) + |amp|^2 class reduction (transposed layout).
        // class = amp bits 14..13 = wg bits 4..3; control q14 = amp bit0 = j&1.
        float pe = 0.f, po = 0.f;
#pragma unroll
        for (int j = 0; j < 32; j++) {
          float p = fmaf(a[j].x, a[j].x, a[j].y * a[j].y);
          if (j & 1) po += p; else pe += p;
        }
        const int c = (wg >> 3) & 3;
        if      (c == 0) { ps0 = pe; ps2 = po; }
        else if (c == 1) { ps1 = pe; ps3 = po; }
        else if (c == 2) { ps2 = pe; ps0 = po; }
        else             { ps3 = pe; ps1 = po; }
      }
    }
    if (l < N_LAYERS - 1) cluster.sync();
  }

  // ---- Reduce class sums: warp -> CTA shared -> cross-CTA (DSMEM) ----
#pragma unroll
  for (int o = 16; o > 0; o >>= 1) {
    ps0 += __shfl_xor_sync(0xffffffffu, ps0, o);
    ps1 += __shfl_xor_sync(0xffffffffu, ps1, o);
    ps2 += __shfl_xor_sync(0xffffffffu, ps2, o);
    ps3 += __shfl_xor_sync(0xffffffffu, ps3, o);
  }
  if ((tid & 31) == 0) {
    atomicAdd(&sred[0], ps0);
    atomicAdd(&sred[1], ps1);
    atomicAdd(&sred[2], ps2);
    atomicAdd(&sred[3], ps3);
  }
  __syncthreads();

  if (rank == 1 && tid < 4) {
    float* dst = cluster.map_shared_rank(sred, 0);
    atomicAdd(dst + tid, sred[tid]);
  }
  cluster.sync();
  if (rank == 0 && tid < 4) out[b * 4 + tid] = sred[tid] * sS2;
}

extern "C" void kernel_launch(void* const* d_in, const int* in_sizes, int n_in,
                              void* d_out, int out_size) {
  const float* x    = (const float*)d_in[0];
  const float* P    = (const float*)d_in[1];
  const float* Q    = (const float*)d_in[2];
  const float* rotp = (const float*)d_in[3];
  const float* gum  = (const float*)d_in[4];
  static bool attr_done = false;
  // Idempotent, deterministic, not a stream op: safe under graph capture.
  cudaFuncSetAttribute(qdarts_kernel,
                       cudaFuncAttributeMaxDynamicSharedMemorySize,
                       (int)SMEM_BYTES);
  (void)attr_done;
  qdarts_kernel<<<BATCHN * 2, NTHREADS, SMEM_BYTES>>>(x, P, Q, rotp, gum,
                                                      (float*)d_out);
}